// round 2
// baseline (speedup 1.0000x reference)
#include <cuda_runtime.h>

// ---------------------------------------------------------------------------
// B=16, N=7, Lq=256, Lp=512, D=768, S=12, Wq=200, Wp=400
// word slots: q 3200, p 6400, n 44800 -> 54400
// out floats: q_pooled[0,12288) p_pooled[12288,24576)
//             q_logits[24576,62976) p_logits[62976,139776) n_pooled[139776,225792)
// ---------------------------------------------------------------------------
#define TOTAL_WORDS 54400
#define OFF_QPOOL 0
#define OFF_PPOOL 12288
#define OFF_QLOG  24576
#define OFF_PLOG  62976
#define OFF_NPOOL 139776

// g_acc[w*13 + 0..11] = logit sums, [w*13+12] = count
__device__ float g_acc[TOTAL_WORDS * 13];
__device__ float g_coef[TOTAL_WORDS];

typedef unsigned long long u64;

__device__ __forceinline__ u64 pack2(float x) {
    u64 r; asm("mov.b64 %0, {%1, %1};" : "=l"(r) : "f"(x)); return r;
}
__device__ __forceinline__ u64 pack2(float lo, float hi) {
    u64 r; asm("mov.b64 %0, {%1, %2};" : "=l"(r) : "f"(lo), "f"(hi)); return r;
}
__device__ __forceinline__ void fma2(u64& a, u64 x, u64 y) {
    asm("fma.rn.f32x2 %0, %1, %2, %0;" : "+l"(a) : "l"(x), "l"(y));
}
__device__ __forceinline__ u64 add2(u64 x, u64 y) {
    u64 r; asm("add.rn.f32x2 %0, %1, %2;" : "=l"(r) : "l"(x), "l"(y)); return r;
}
__device__ __forceinline__ float2 unpack2(u64 v) {
    float2 r; asm("mov.b64 {%0, %1}, %2;" : "=f"(r.x), "=f"(r.y) : "l"(v)); return r;
}

// ---------------------------------------------------------------------------
// Kernel A: per-token projection h[768]@W[768x12] + segment atomics.
// Warp tiling: sub = lane&7 covers d = sub*4 + 32*i + k (i 0..23, k 0..3)
//              grp = lane>>3, tokens per pass = grp + 4*tt, tt in {0,1} -> 8
// Each LDG.128 covers 4 rows x 128B = 4 full lines (nL=4, optimal).
// Weights in smem chunked: chunk c=d>>2 holds 6 scope-pairs x 4 k, pitch 25
// u64 -> sub bank offsets {0,18,4,22,8,26,12,30}: conflict-free broadcast.
// Passes: 69632 tokens / 8 = 8704 (q 512, p 1024, n 7168).
// ---------------------------------------------------------------------------
#define WSLOT 25
#define NPASS_TOTAL 8704
#define KA_BLOCKS 888   // 148 SM * 6 blocks

__global__ __launch_bounds__(128, 6) void kA(
    const float* __restrict__ qh, const float* __restrict__ ph, const float* __restrict__ nh,
    const int* __restrict__ qw, const int* __restrict__ pw, const int* __restrict__ nwid,
    const float* __restrict__ projw)
{
    __shared__ u64 sw[192 * WSLOT];   // 38400 bytes -> 6 CTAs/SM
    for (int idx = threadIdx.x; idx < 768 * 6; idx += 128) {
        int d = idx / 6, j = idx % 6;
        int c = d >> 2, k = d & 3;
        sw[c * WSLOT + j * 4 + k] = pack2(projw[d * 12 + 2 * j], projw[d * 12 + 2 * j + 1]);
    }
    __syncthreads();

    const int lane = threadIdx.x & 31;
    const int sub  = lane & 7;
    const int grp  = lane >> 3;
    const int gw   = (blockIdx.x * blockDim.x + threadIdx.x) >> 5;
    const int nwarps = (KA_BLOCKS * 128) >> 5;

    for (int p = gw; p < NPASS_TOTAL; p += nwarps) {
        const float* hid; const int* wid; int logL, W, wb, lp;
        if (p < 512)       { hid = qh; wid = qw;   logL = 8; W = 200; wb = 0;    lp = p; }
        else if (p < 1536) { hid = ph; wid = pw;   logL = 9; W = 400; wb = 3200; lp = p - 512; }
        else               { hid = nh; wid = nwid; logL = 9; W = 400; wb = 9600; lp = p - 1536; }

        const int tokBase = lp << 3;                 // 8 tokens per pass
        const int m = tokBase >> logL;               // sample index within tensor
        const float* hb = hid + (size_t)tokBase * 768 + sub * 4;

        u64 acc[2][6];
        #pragma unroll
        for (int j = 0; j < 6; j++) { acc[0][j] = 0ull; acc[1][j] = 0ull; }

        #pragma unroll 2
        for (int i = 0; i < 24; i++) {
            float4 v0 = *(const float4*)(hb + (size_t)grp * 768       + i * 32);
            float4 v1 = *(const float4*)(hb + (size_t)(grp + 4) * 768 + i * 32);
            const u64* wr = sw + (sub + 8 * i) * WSLOT;
            float a0[4] = {v0.x, v0.y, v0.z, v0.w};
            float a1[4] = {v1.x, v1.y, v1.z, v1.w};
            #pragma unroll
            for (int k = 0; k < 4; k++) {
                u64 h0 = pack2(a0[k]);
                u64 h1 = pack2(a1[k]);
                #pragma unroll
                for (int j = 0; j < 6; j++) {
                    u64 w = wr[j * 4 + k];
                    fma2(acc[0][j], h0, w);
                    fma2(acc[1][j], h1, w);
                }
            }
        }

        // reduce across the 8 sub-lanes (xor 1,2,4 stay inside the octet)
        #pragma unroll
        for (int tt = 0; tt < 2; tt++)
            #pragma unroll
            for (int j = 0; j < 6; j++) {
                u64 v = acc[tt][j];
                v = add2(v, __shfl_xor_sync(0xffffffffu, v, 1));
                v = add2(v, __shfl_xor_sync(0xffffffffu, v, 2));
                v = add2(v, __shfl_xor_sync(0xffffffffu, v, 4));
                acc[tt][j] = v;
            }

        if (sub == 0) {
            #pragma unroll
            for (int tt = 0; tt < 2; tt++) {
                int tok = tokBase + grp + 4 * tt;
                int w = wid[tok];
                float* ls = g_acc + ((size_t)wb + (size_t)m * W + w) * 13;
                #pragma unroll
                for (int j = 0; j < 6; j++) {
                    float2 f = unpack2(acc[tt][j]);
                    atomicAdd(ls + 2 * j,     f.x);
                    atomicAdd(ls + 2 * j + 1, f.y);
                }
                atomicAdd(ls + 12, 1.0f);
            }
        }
    }
}

// ---------------------------------------------------------------------------
// Kernel B: per sample — scope softmax -> importance, masked word softmax ->
// per-word coefficient weight/count; writes q/p logits. 144 blocks x 128.
// ---------------------------------------------------------------------------
__global__ __launch_bounds__(128) void kB(const float* __restrict__ projb,
                                          const float* __restrict__ simp,
                                          float* __restrict__ out)
{
    const int blk = blockIdx.x;
    int W, wb; float* lout = nullptr;
    if (blk < 16)      { W = 200; wb = blk * 200;                    lout = out + OFF_QLOG + blk * 200 * 12; }
    else if (blk < 32) { int m = blk - 16; W = 400; wb = 3200 + m * 400; lout = out + OFF_PLOG + m * 400 * 12; }
    else               { int m = blk - 32; W = 400; wb = 9600 + m * 400; }

    __shared__ float impbuf[400];
    __shared__ float red[4];
    const int tid = threadIdx.x;

    float b[12], si[12];
    #pragma unroll
    for (int s = 0; s < 12; s++) { b[s] = projb[s]; si[s] = simp[s]; }

    for (int w = tid; w < W; w += 128) {
        const float* ls = g_acc + (size_t)(wb + w) * 13;
        float c = ls[12];
        float imp;
        if (c > 0.f) {
            float l[12], mx = -1e30f;
            float invc = 1.f / c;
            #pragma unroll
            for (int s = 0; s < 12; s++) {
                l[s] = ls[s] * invc + b[s];
                mx = fmaxf(mx, l[s]);
            }
            float se = 0.f, ai = 0.f;
            #pragma unroll
            for (int s = 0; s < 12; s++) {
                float e = __expf(l[s] - mx);
                se += e; ai += e * si[s];
            }
            imp = ai / se;
            if (lout) {
                #pragma unroll
                for (int s = 0; s < 12; s++) lout[w * 12 + s] = l[s];
            }
        } else {
            imp = -1e4f;
            if (lout) {
                #pragma unroll
                for (int s = 0; s < 12; s++) lout[w * 12 + s] = 0.f;
            }
        }
        impbuf[w] = imp;
    }
    __syncthreads();

    float mx = -1e30f;
    for (int w = tid; w < W; w += 128) mx = fmaxf(mx, impbuf[w]);
    #pragma unroll
    for (int o = 16; o; o >>= 1) mx = fmaxf(mx, __shfl_xor_sync(0xffffffffu, mx, o));
    if ((tid & 31) == 0) red[tid >> 5] = mx;
    __syncthreads();
    mx = fmaxf(fmaxf(red[0], red[1]), fmaxf(red[2], red[3]));
    __syncthreads();

    float se = 0.f;
    for (int w = tid; w < W; w += 128) se += __expf(impbuf[w] - mx);
    #pragma unroll
    for (int o = 16; o; o >>= 1) se += __shfl_xor_sync(0xffffffffu, se, o);
    if ((tid & 31) == 0) red[tid >> 5] = se;
    __syncthreads();
    se = red[0] + red[1] + red[2] + red[3];
    const float inv = 1.f / se;

    for (int w = tid; w < W; w += 128) {
        float c = g_acc[(size_t)(wb + w) * 13 + 12];
        g_coef[wb + w] = (c > 0.f) ? (__expf(impbuf[w] - mx) * inv) / c : 0.f;
    }
}

// ---------------------------------------------------------------------------
// Kernel C: pooled[m,:] += sum over 64-token slab coef[m, wid] * h[m,tok,:]
// 1088 blocks x 192 threads, float4/thread covers D=768.
// ---------------------------------------------------------------------------
__global__ __launch_bounds__(192) void kC(
    const float* __restrict__ qh, const float* __restrict__ ph, const float* __restrict__ nh,
    const int* __restrict__ qw, const int* __restrict__ pw, const int* __restrict__ nwid,
    float* __restrict__ out)
{
    const int blk = blockIdx.x;
    const float* hid; const int* wid; int L, wb, m, slab; float* po;
    if (blk < 64)       { m = blk >> 2;  slab = blk & 3; hid = qh; wid = qw;   L = 256; wb = m * 200;        po = out + OFF_QPOOL + m * 768; }
    else if (blk < 192) { int b2 = blk - 64;  m = b2 >> 3; slab = b2 & 7; hid = ph; wid = pw;   L = 512; wb = 3200 + m * 400; po = out + OFF_PPOOL + m * 768; }
    else                { int b2 = blk - 192; m = b2 >> 3; slab = b2 & 7; hid = nh; wid = nwid; L = 512; wb = 9600 + m * 400; po = out + OFF_NPOOL + m * 768; }

    __shared__ float cf[64];
    const int tid = threadIdx.x;
    const int t0 = slab * 64;
    if (tid < 64) cf[tid] = g_coef[wb + wid[m * L + t0 + tid]];
    __syncthreads();

    const float* hp = hid + (size_t)(m * L + t0) * 768 + tid * 4;
    float ax = 0.f, ay = 0.f, az = 0.f, aw = 0.f;
    #pragma unroll 8
    for (int t = 0; t < 64; t++) {
        float c = cf[t];
        float4 v = *(const float4*)(hp + (size_t)t * 768);
        ax += c * v.x; ay += c * v.y; az += c * v.z; aw += c * v.w;
    }
    float* o = po + tid * 4;
    atomicAdd(o + 0, ax);
    atomicAdd(o + 1, ay);
    atomicAdd(o + 2, az);
    atomicAdd(o + 3, aw);
}

// ---------------------------------------------------------------------------
extern "C" void kernel_launch(void* const* d_in, const int* in_sizes, int n_in,
                              void* d_out, int out_size)
{
    const float* qh    = (const float*)d_in[0];
    const float* ph    = (const float*)d_in[1];
    const float* nh    = (const float*)d_in[2];
    const float* projw = (const float*)d_in[3];
    const float* projb = (const float*)d_in[4];
    const float* simp  = (const float*)d_in[5];
    const int*   qw    = (const int*)d_in[6];
    const int*   pw    = (const int*)d_in[7];
    const int*   nwid  = (const int*)d_in[8];
    float* out = (float*)d_out;

    void* pacc = nullptr; cudaGetSymbolAddress(&pacc, g_acc);
    cudaMemsetAsync(pacc, 0, sizeof(float) * TOTAL_WORDS * 13);
    cudaMemsetAsync(out + OFF_QPOOL, 0, sizeof(float) * 24576);   // q_pooled + p_pooled
    cudaMemsetAsync(out + OFF_NPOOL, 0, sizeof(float) * 86016);   // n_pooled

    kA<<<KA_BLOCKS, 128>>>(qh, ph, nh, qw, pw, nwid, projw);
    kB<<<144, 128>>>(projb, simp, out);
    kC<<<1088, 192>>>(qh, ph, nh, qw, pw, nwid, out);
}

// round 3
// speedup vs baseline: 1.0578x; 1.0578x over previous
#include <cuda_runtime.h>

// ---------------------------------------------------------------------------
// B=16, N=7, Lq=256, Lp=512, D=768, S=12, Wq=200, Wp=400
// word slots: q 3200, p 6400, n 44800 -> 54400
// out floats: q_pooled[0,12288) p_pooled[12288,24576)
//             q_logits[24576,62976) p_logits[62976,139776) n_pooled[139776,225792)
// ---------------------------------------------------------------------------
#define TOTAL_WORDS 54400
#define OFF_QPOOL 0
#define OFF_PPOOL 12288
#define OFF_QLOG  24576
#define OFF_PLOG  62976
#define OFF_NPOOL 139776

// g_acc[w*13 + 0..11] = logit sums, [w*13+12] = count
__device__ float g_acc[TOTAL_WORDS * 13];
__device__ float g_coef[TOTAL_WORDS];

typedef unsigned long long u64;

__device__ __forceinline__ u64 pack2(float x) {
    u64 r; asm("mov.b64 %0, {%1, %1};" : "=l"(r) : "f"(x)); return r;
}
__device__ __forceinline__ u64 pack2(float lo, float hi) {
    u64 r; asm("mov.b64 %0, {%1, %2};" : "=l"(r) : "f"(lo), "f"(hi)); return r;
}
__device__ __forceinline__ void fma2(u64& a, u64 x, u64 y) {
    asm("fma.rn.f32x2 %0, %1, %2, %0;" : "+l"(a) : "l"(x), "l"(y));
}
__device__ __forceinline__ u64 add2(u64 x, u64 y) {
    u64 r; asm("add.rn.f32x2 %0, %1, %2;" : "=l"(r) : "l"(x), "l"(y)); return r;
}
__device__ __forceinline__ float2 unpack2(u64 v) {
    float2 r; asm("mov.b64 {%0, %1}, %2;" : "=f"(r.x), "=f"(r.y) : "l"(v)); return r;
}

// ---------------------------------------------------------------------------
// Kernel A: per-token projection h[768]@W[768x12] + segment atomics.
// Warp tiling (hybrid of R1/R2):
//   sub = lane&7  covers d = sub*4 + 32*i + k   (i 0..23, k 0..3)
//   grp = lane>>3 (0..3), tokens = grp + 4*tt, tt in 0..3  -> 16 tokens/pass
// Each LDG.128: 8 subs x 16B = 128B contiguous per token row, 4 tokens (grp)
//   -> 4 cache lines per instruction (optimal).
// LDS amortization: weights for a d swept once per 16 tokens ->
//   24i * 24 LDS.64 / 16 tokens = 36 warp-LDS/token (R1 level).
// Weights in smem chunked by c=d>>2, pitch 25 u64: sub banks
//   {0,18,4,22,8,26,12,30} -> conflict-free.
// Passes: 69632/16 = 4352 (q 256, p 512, n 3584). Grid 544*4 warps = 2176
//   -> exactly 2 passes per warp.
// ---------------------------------------------------------------------------
#define WSLOT 25
#define NPASS_TOTAL 4352
#define KA_BLOCKS 544

__global__ __launch_bounds__(128) void kA(
    const float* __restrict__ qh, const float* __restrict__ ph, const float* __restrict__ nh,
    const int* __restrict__ qw, const int* __restrict__ pw, const int* __restrict__ nwid,
    const float* __restrict__ projw)
{
    __shared__ u64 sw[192 * WSLOT];   // 38400 bytes
    for (int idx = threadIdx.x; idx < 768 * 6; idx += 128) {
        int d = idx / 6, j = idx % 6;
        int c = d >> 2, k = d & 3;
        sw[c * WSLOT + j * 4 + k] = pack2(projw[d * 12 + 2 * j], projw[d * 12 + 2 * j + 1]);
    }
    __syncthreads();

    const int lane = threadIdx.x & 31;
    const int sub  = lane & 7;
    const int grp  = lane >> 3;
    const int gw   = (blockIdx.x * blockDim.x + threadIdx.x) >> 5;
    const int nwarps = (KA_BLOCKS * 128) >> 5;

    for (int p = gw; p < NPASS_TOTAL; p += nwarps) {
        const float* hid; const int* wid; int logL, W, wb, lp;
        if (p < 256)      { hid = qh; wid = qw;   logL = 8; W = 200; wb = 0;    lp = p; }
        else if (p < 768) { hid = ph; wid = pw;   logL = 9; W = 400; wb = 3200; lp = p - 256; }
        else              { hid = nh; wid = nwid; logL = 9; W = 400; wb = 9600; lp = p - 768; }

        const int tokBase = lp << 4;                 // 16 tokens per pass
        const int m = tokBase >> logL;               // sample index within tensor
        const float* hb = hid + (size_t)tokBase * 768 + sub * 4;

        u64 acc[4][6];
        #pragma unroll
        for (int tt = 0; tt < 4; tt++)
            #pragma unroll
            for (int j = 0; j < 6; j++) acc[tt][j] = 0ull;

        #pragma unroll 2
        for (int i = 0; i < 24; i++) {
            float ha[4][4];
            #pragma unroll
            for (int tt = 0; tt < 4; tt++) {
                float4 v = *(const float4*)(hb + (size_t)(grp + 4 * tt) * 768 + i * 32);
                ha[tt][0] = v.x; ha[tt][1] = v.y; ha[tt][2] = v.z; ha[tt][3] = v.w;
            }
            const u64* wr = sw + (sub + 8 * i) * WSLOT;
            #pragma unroll
            for (int k = 0; k < 4; k++) {
                u64 w0 = wr[0 * 4 + k];
                u64 w1 = wr[1 * 4 + k];
                u64 w2 = wr[2 * 4 + k];
                u64 w3 = wr[3 * 4 + k];
                u64 w4 = wr[4 * 4 + k];
                u64 w5 = wr[5 * 4 + k];
                #pragma unroll
                for (int tt = 0; tt < 4; tt++) {
                    u64 h2 = pack2(ha[tt][k]);
                    fma2(acc[tt][0], h2, w0);
                    fma2(acc[tt][1], h2, w1);
                    fma2(acc[tt][2], h2, w2);
                    fma2(acc[tt][3], h2, w3);
                    fma2(acc[tt][4], h2, w4);
                    fma2(acc[tt][5], h2, w5);
                }
            }
        }

        // reduce across the 8 sub-lanes (xor 1,2,4 stay inside the octet)
        #pragma unroll
        for (int tt = 0; tt < 4; tt++)
            #pragma unroll
            for (int j = 0; j < 6; j++) {
                u64 v = acc[tt][j];
                v = add2(v, __shfl_xor_sync(0xffffffffu, v, 1));
                v = add2(v, __shfl_xor_sync(0xffffffffu, v, 2));
                v = add2(v, __shfl_xor_sync(0xffffffffu, v, 4));
                acc[tt][j] = v;
            }

        if (sub == 0) {
            #pragma unroll
            for (int tt = 0; tt < 4; tt++) {
                int tok = tokBase + grp + 4 * tt;
                int w = wid[tok];
                float* ls = g_acc + ((size_t)wb + (size_t)m * W + w) * 13;
                #pragma unroll
                for (int j = 0; j < 6; j++) {
                    float2 f = unpack2(acc[tt][j]);
                    atomicAdd(ls + 2 * j,     f.x);
                    atomicAdd(ls + 2 * j + 1, f.y);
                }
                atomicAdd(ls + 12, 1.0f);
            }
        }
    }
}

// ---------------------------------------------------------------------------
// Kernel B: per sample — scope softmax -> importance, masked word softmax ->
// per-word coefficient weight/count; writes q/p logits. 144 blocks x 128.
// ---------------------------------------------------------------------------
__global__ __launch_bounds__(128) void kB(const float* __restrict__ projb,
                                          const float* __restrict__ simp,
                                          float* __restrict__ out)
{
    const int blk = blockIdx.x;
    int W, wb; float* lout = nullptr;
    if (blk < 16)      { W = 200; wb = blk * 200;                    lout = out + OFF_QLOG + blk * 200 * 12; }
    else if (blk < 32) { int m = blk - 16; W = 400; wb = 3200 + m * 400; lout = out + OFF_PLOG + m * 400 * 12; }
    else               { int m = blk - 32; W = 400; wb = 9600 + m * 400; }

    __shared__ float impbuf[400];
    __shared__ float red[4];
    const int tid = threadIdx.x;

    float b[12], si[12];
    #pragma unroll
    for (int s = 0; s < 12; s++) { b[s] = projb[s]; si[s] = simp[s]; }

    for (int w = tid; w < W; w += 128) {
        const float* ls = g_acc + (size_t)(wb + w) * 13;
        float c = ls[12];
        float imp;
        if (c > 0.f) {
            float l[12], mx = -1e30f;
            float invc = 1.f / c;
            #pragma unroll
            for (int s = 0; s < 12; s++) {
                l[s] = ls[s] * invc + b[s];
                mx = fmaxf(mx, l[s]);
            }
            float se = 0.f, ai = 0.f;
            #pragma unroll
            for (int s = 0; s < 12; s++) {
                float e = __expf(l[s] - mx);
                se += e; ai += e * si[s];
            }
            imp = ai / se;
            if (lout) {
                #pragma unroll
                for (int s = 0; s < 12; s++) lout[w * 12 + s] = l[s];
            }
        } else {
            imp = -1e4f;
            if (lout) {
                #pragma unroll
                for (int s = 0; s < 12; s++) lout[w * 12 + s] = 0.f;
            }
        }
        impbuf[w] = imp;
    }
    __syncthreads();

    float mx = -1e30f;
    for (int w = tid; w < W; w += 128) mx = fmaxf(mx, impbuf[w]);
    #pragma unroll
    for (int o = 16; o; o >>= 1) mx = fmaxf(mx, __shfl_xor_sync(0xffffffffu, mx, o));
    if ((tid & 31) == 0) red[tid >> 5] = mx;
    __syncthreads();
    mx = fmaxf(fmaxf(red[0], red[1]), fmaxf(red[2], red[3]));
    __syncthreads();

    float se = 0.f;
    for (int w = tid; w < W; w += 128) se += __expf(impbuf[w] - mx);
    #pragma unroll
    for (int o = 16; o; o >>= 1) se += __shfl_xor_sync(0xffffffffu, se, o);
    if ((tid & 31) == 0) red[tid >> 5] = se;
    __syncthreads();
    se = red[0] + red[1] + red[2] + red[3];
    const float inv = 1.f / se;

    for (int w = tid; w < W; w += 128) {
        float c = g_acc[(size_t)(wb + w) * 13 + 12];
        g_coef[wb + w] = (c > 0.f) ? (__expf(impbuf[w] - mx) * inv) / c : 0.f;
    }
}

// ---------------------------------------------------------------------------
// Kernel C: pooled[m,:] += sum over 128-token slab coef[m, wid] * h[m,tok,:]
// 544 blocks x 192 threads, float4/thread covers D=768.
// Blocks: q 16*2=32, p 16*4=64, n 112*4=448.
// ---------------------------------------------------------------------------
__global__ __launch_bounds__(192) void kC(
    const float* __restrict__ qh, const float* __restrict__ ph, const float* __restrict__ nh,
    const int* __restrict__ qw, const int* __restrict__ pw, const int* __restrict__ nwid,
    float* __restrict__ out)
{
    const int blk = blockIdx.x;
    const float* hid; const int* wid; int L, wb, m, slab; float* po;
    if (blk < 32)      { m = blk >> 1;  slab = blk & 1; hid = qh; wid = qw;   L = 256; wb = m * 200;        po = out + OFF_QPOOL + m * 768; }
    else if (blk < 96) { int b2 = blk - 32; m = b2 >> 2; slab = b2 & 3; hid = ph; wid = pw;   L = 512; wb = 3200 + m * 400; po = out + OFF_PPOOL + m * 768; }
    else               { int b2 = blk - 96; m = b2 >> 2; slab = b2 & 3; hid = nh; wid = nwid; L = 512; wb = 9600 + m * 400; po = out + OFF_NPOOL + m * 768; }

    __shared__ float cf[128];
    const int tid = threadIdx.x;
    const int t0 = slab * 128;
    if (tid < 128) cf[tid] = g_coef[wb + wid[m * L + t0 + tid]];
    __syncthreads();

    const float* hp = hid + (size_t)(m * L + t0) * 768 + tid * 4;
    float ax = 0.f, ay = 0.f, az = 0.f, aw = 0.f;
    #pragma unroll 8
    for (int t = 0; t < 128; t++) {
        float c = cf[t];
        float4 v = *(const float4*)(hp + (size_t)t * 768);
        ax += c * v.x; ay += c * v.y; az += c * v.z; aw += c * v.w;
    }
    float* o = po + tid * 4;
    atomicAdd(o + 0, ax);
    atomicAdd(o + 1, ay);
    atomicAdd(o + 2, az);
    atomicAdd(o + 3, aw);
}

// ---------------------------------------------------------------------------
extern "C" void kernel_launch(void* const* d_in, const int* in_sizes, int n_in,
                              void* d_out, int out_size)
{
    const float* qh    = (const float*)d_in[0];
    const float* ph    = (const float*)d_in[1];
    const float* nh    = (const float*)d_in[2];
    const float* projw = (const float*)d_in[3];
    const float* projb = (const float*)d_in[4];
    const float* simp  = (const float*)d_in[5];
    const int*   qw    = (const int*)d_in[6];
    const int*   pw    = (const int*)d_in[7];
    const int*   nwid  = (const int*)d_in[8];
    float* out = (float*)d_out;

    void* pacc = nullptr; cudaGetSymbolAddress(&pacc, g_acc);
    cudaMemsetAsync(pacc, 0, sizeof(float) * TOTAL_WORDS * 13);
    cudaMemsetAsync(out + OFF_QPOOL, 0, sizeof(float) * 24576);   // q_pooled + p_pooled
    cudaMemsetAsync(out + OFF_NPOOL, 0, sizeof(float) * 86016);   // n_pooled

    kA<<<KA_BLOCKS, 128>>>(qh, ph, nh, qw, pw, nwid, projw);
    kB<<<144, 128>>>(projb, simp, out);
    kC<<<544, 192>>>(qh, ph, nh, qw, pw, nwid, out);
}